// round 2
// baseline (speedup 1.0000x reference)
#include <cuda_runtime.h>
#include <math.h>

// Problem constants
#define NTOK   3137            // 1 + 16*196
#define BDIM   4
#define HEADS  16
#define HD     64
#define DIM    1024
#define QKVDIM 3072
#define M_ROWS (BDIM*NTOK)     // 12548
#define FRAMES 16
#define SEQ    196
#define NKEY   197             // SEQ + cls

// Scratch (allocation-free rule: __device__ globals)
__device__ float g_q[(size_t)BDIM*HEADS*NTOK*HD];
__device__ float g_k[(size_t)BDIM*HEADS*NTOK*HD];
__device__ float g_v[(size_t)BDIM*HEADS*NTOK*HD];
__device__ float g_o[(size_t)BDIM*HEADS*NTOK*HD];

// ---------------------------------------------------------------------------
// SGEMM tiles
// ---------------------------------------------------------------------------
#define BM 128
#define BN 64
#define BK 16
#define PADA 4
#define PADB 4

// QKV: out[m][o] = sum_k x[m][k]*w[o][k] + b[o], scattered to g_q/g_k/g_v in
// head-major layout [(b*H+h)][n][d]; q scaled by hd^-0.5 = 0.125.
__global__ __launch_bounds__(256) void qkv_gemm(const float* __restrict__ x,
                                                const float* __restrict__ w,
                                                const float* __restrict__ bias) {
    __shared__ __align__(16) float As[BK][BM+PADA];
    __shared__ __align__(16) float Bs[BK][BN+PADB];
    const int tid = threadIdx.x;
    const int tm0 = blockIdx.x * BM;
    const int tn0 = blockIdx.y * BN;
    const int tx = tid & 15;   // n-dir, 4 outputs
    const int ty = tid >> 4;   // m-dir, 8 outputs

    float acc[8][4];
    #pragma unroll
    for (int i = 0; i < 8; i++)
        #pragma unroll
        for (int j = 0; j < 4; j++) acc[i][j] = 0.f;

    for (int k0 = 0; k0 < DIM; k0 += BK) {
        #pragma unroll
        for (int l = 0; l < 2; l++) {
            int idx = tid + l*256;        // 0..511
            int row = idx >> 2;           // 0..127
            int kc  = (idx & 3) << 2;     // 0,4,8,12
            int gm  = tm0 + row;
            float4 t = make_float4(0.f,0.f,0.f,0.f);
            if (gm < M_ROWS) t = *(const float4*)(x + (size_t)gm*DIM + k0 + kc);
            As[kc+0][row] = t.x; As[kc+1][row] = t.y;
            As[kc+2][row] = t.z; As[kc+3][row] = t.w;
        }
        {
            int row = tid >> 2;           // 0..63
            int kc  = (tid & 3) << 2;
            float4 t = *(const float4*)(w + (size_t)(tn0+row)*DIM + k0 + kc);
            Bs[kc+0][row] = t.x; Bs[kc+1][row] = t.y;
            Bs[kc+2][row] = t.z; Bs[kc+3][row] = t.w;
        }
        __syncthreads();
        #pragma unroll
        for (int kk = 0; kk < BK; kk++) {
            float4 a0 = *(const float4*)&As[kk][ty*8];
            float4 a1 = *(const float4*)&As[kk][ty*8+4];
            float4 b0 = *(const float4*)&Bs[kk][tx*4];
            float a[8] = {a0.x,a0.y,a0.z,a0.w,a1.x,a1.y,a1.z,a1.w};
            float bb[4] = {b0.x,b0.y,b0.z,b0.w};
            #pragma unroll
            for (int i = 0; i < 8; i++)
                #pragma unroll
                for (int j = 0; j < 4; j++)
                    acc[i][j] += a[i]*bb[j];
        }
        __syncthreads();
    }

    #pragma unroll
    for (int i = 0; i < 8; i++) {
        int gm = tm0 + ty*8 + i;
        if (gm >= M_ROWS) continue;
        int b = gm / NTOK;
        int n = gm - b*NTOK;
        #pragma unroll
        for (int j = 0; j < 4; j++) {
            int gn = tn0 + tx*4 + j;
            float val = acc[i][j] + bias[gn];
            int part = gn >> 10;
            int rem  = gn & 1023;
            int h = rem >> 6;
            int d = rem & 63;
            size_t off = (((size_t)(b*HEADS + h))*NTOK + n)*HD + d;
            if (part == 0)      g_q[off] = val * 0.125f;
            else if (part == 1) g_k[off] = val;
            else                g_v[off] = val;
        }
    }
}

// Proj: out[m][o] = sum_k A[m][k]*w[o][k] + b[o] where
// A[m][k] = g_o[((b*H + k/64)*NTOK + n)*64 + k%64]   (head -> channel gather)
__global__ __launch_bounds__(256) void proj_gemm(const float* __restrict__ w,
                                                 const float* __restrict__ bias,
                                                 float* __restrict__ out) {
    __shared__ __align__(16) float As[BK][BM+PADA];
    __shared__ __align__(16) float Bs[BK][BN+PADB];
    const int tid = threadIdx.x;
    const int tm0 = blockIdx.x * BM;
    const int tn0 = blockIdx.y * BN;
    const int tx = tid & 15;
    const int ty = tid >> 4;

    // Hoist the per-thread A-row decomposition out of the k-loop
    const int a_idx0 = tid;          // rows this thread loads: idx>>2 for idx=tid, tid+256
    int a_b[2], a_n[2], a_valid[2];
    #pragma unroll
    for (int l = 0; l < 2; l++) {
        int row = (tid + l*256) >> 2;
        int gm  = tm0 + row;
        a_valid[l] = (gm < M_ROWS);
        int b = a_valid[l] ? (gm / NTOK) : 0;
        a_b[l] = b;
        a_n[l] = gm - b*NTOK;
    }
    (void)a_idx0;

    float acc[8][4];
    #pragma unroll
    for (int i = 0; i < 8; i++)
        #pragma unroll
        for (int j = 0; j < 4; j++) acc[i][j] = 0.f;

    for (int k0 = 0; k0 < DIM; k0 += BK) {
        #pragma unroll
        for (int l = 0; l < 2; l++) {
            int idx = tid + l*256;
            int row = idx >> 2;
            int kc  = (idx & 3) << 2;
            float4 t = make_float4(0.f,0.f,0.f,0.f);
            if (a_valid[l]) {
                int k = k0 + kc;
                int h = k >> 6;
                int d = k & 63;
                t = *(const float4*)(g_o + (((size_t)(a_b[l]*HEADS + h))*NTOK + a_n[l])*HD + d);
            }
            As[kc+0][row] = t.x; As[kc+1][row] = t.y;
            As[kc+2][row] = t.z; As[kc+3][row] = t.w;
        }
        {
            int row = tid >> 2;
            int kc  = (tid & 3) << 2;
            float4 t = *(const float4*)(w + (size_t)(tn0+row)*DIM + k0 + kc);
            Bs[kc+0][row] = t.x; Bs[kc+1][row] = t.y;
            Bs[kc+2][row] = t.z; Bs[kc+3][row] = t.w;
        }
        __syncthreads();
        #pragma unroll
        for (int kk = 0; kk < BK; kk++) {
            float4 a0 = *(const float4*)&As[kk][ty*8];
            float4 a1 = *(const float4*)&As[kk][ty*8+4];
            float4 b0 = *(const float4*)&Bs[kk][tx*4];
            float a[8] = {a0.x,a0.y,a0.z,a0.w,a1.x,a1.y,a1.z,a1.w};
            float bb[4] = {b0.x,b0.y,b0.z,b0.w};
            #pragma unroll
            for (int i = 0; i < 8; i++)
                #pragma unroll
                for (int j = 0; j < 4; j++)
                    acc[i][j] += a[i]*bb[j];
        }
        __syncthreads();
    }

    #pragma unroll
    for (int i = 0; i < 8; i++) {
        int gm = tm0 + ty*8 + i;
        if (gm >= M_ROWS) continue;
        #pragma unroll
        for (int j = 0; j < 4; j++) {
            int gn = tn0 + tx*4 + j;
            out[(size_t)gm*DIM + gn] = acc[i][j] + bias[gn];
        }
    }
}

// ---------------------------------------------------------------------------
// Divided (spatial) attention: 1 CTA per group g = bh*16 + frame.
// Keys = [cls] + 196 frame tokens of this (bh, frame); queries = 196 tokens.
// One thread per query, flash-style online softmax, K/V staged in smem.
// ---------------------------------------------------------------------------
__global__ __launch_bounds__(256) void div_attn(const int* __restrict__ mask) {
    extern __shared__ float sh[];
    float* kk = sh;                       // NKEY*HD
    float* vv = sh + NKEY*HD;             // NKEY*HD
    int*   mk = (int*)(vv + NKEY*HD);     // NKEY

    const int g   = blockIdx.x;
    const int bh  = g >> 4;
    const int fi  = g & 15;
    const int b   = bh >> 4;
    const int tid = threadIdx.x;

    for (int idx = tid; idx < NKEY*HD; idx += 256) {
        int j = idx >> 6;
        int d = idx & 63;
        int tok = (j == 0) ? 0 : (fi*SEQ + j);   // 1 + fi*196 + (j-1)
        size_t off = ((size_t)bh*NTOK + tok)*HD + d;
        kk[idx] = g_k[off];
        vv[idx] = g_v[off];
    }
    for (int j = tid; j < NKEY; j += 256) {
        int tok = (j == 0) ? 0 : (fi*SEQ + j);
        mk[j] = mask[b*NTOK + tok];
    }
    __syncthreads();

    if (tid < SEQ) {
        int qi = 1 + fi*SEQ + tid;
        size_t qoff = ((size_t)bh*NTOK + qi)*HD;
        float q[HD];
        #pragma unroll
        for (int d = 0; d < HD; d += 4) {
            float4 t = *(const float4*)(g_q + qoff + d);
            q[d] = t.x; q[d+1] = t.y; q[d+2] = t.z; q[d+3] = t.w;
        }
        float o[HD];
        #pragma unroll
        for (int d = 0; d < HD; d++) o[d] = 0.f;
        float m = -INFINITY, l = 0.f;

        const float4* kk4 = (const float4*)kk;
        const float4* vv4 = (const float4*)vv;
        for (int j = 0; j < NKEY; j++) {
            if (mk[j] == 0) continue;
            float s0 = 0.f, s1 = 0.f, s2 = 0.f, s3 = 0.f;
            #pragma unroll
            for (int d = 0; d < 16; d++) {
                float4 kv = kk4[j*16 + d];
                s0 += q[4*d+0]*kv.x;
                s1 += q[4*d+1]*kv.y;
                s2 += q[4*d+2]*kv.z;
                s3 += q[4*d+3]*kv.w;
            }
            float s = (s0+s1) + (s2+s3);
            float mn = fmaxf(m, s);
            float corr = __expf(m - mn);
            float p    = __expf(s - mn);
            l = l*corr + p;
            #pragma unroll
            for (int d = 0; d < 16; d++) {
                float4 tv = vv4[j*16 + d];
                o[4*d+0] = o[4*d+0]*corr + p*tv.x;
                o[4*d+1] = o[4*d+1]*corr + p*tv.y;
                o[4*d+2] = o[4*d+2]*corr + p*tv.z;
                o[4*d+3] = o[4*d+3]*corr + p*tv.w;
            }
            m = mn;
        }
        float inv = 1.f / l;
        #pragma unroll
        for (int d = 0; d < HD; d += 4) {
            float4 t = make_float4(o[d]*inv, o[d+1]*inv, o[d+2]*inv, o[d+3]*inv);
            *(float4*)(g_o + qoff + d) = t;
        }
    }
}

// ---------------------------------------------------------------------------
// cls-token attention: 1 CTA per (b,h); 128 threads split the 3137 keys,
// flash partials (m,l,o[64]) per thread, then smem reduce.
// ---------------------------------------------------------------------------
__global__ __launch_bounds__(128) void cls_attn(const int* __restrict__ mask) {
    __shared__ float red[128][HD+1];
    __shared__ float sm_[128];
    __shared__ float sl_[128];

    const int bh  = blockIdx.x;
    const int b   = bh >> 4;
    const int tid = threadIdx.x;
    const size_t base = (size_t)bh*NTOK*HD;

    float q[HD];
    #pragma unroll
    for (int d = 0; d < HD; d += 4) {
        float4 t = *(const float4*)(g_q + base + d);
        q[d] = t.x; q[d+1] = t.y; q[d+2] = t.z; q[d+3] = t.w;
    }
    float o[HD];
    #pragma unroll
    for (int d = 0; d < HD; d++) o[d] = 0.f;
    float m = -INFINITY, l = 0.f;

    for (int j = tid; j < NTOK; j += 128) {
        if (mask[b*NTOK + j] == 0) continue;
        const float4* kp = (const float4*)(g_k + base + (size_t)j*HD);
        const float4* vp = (const float4*)(g_v + base + (size_t)j*HD);
        float s0 = 0.f, s1 = 0.f, s2 = 0.f, s3 = 0.f;
        #pragma unroll
        for (int d = 0; d < 16; d++) {
            float4 kv = kp[d];
            s0 += q[4*d+0]*kv.x;
            s1 += q[4*d+1]*kv.y;
            s2 += q[4*d+2]*kv.z;
            s3 += q[4*d+3]*kv.w;
        }
        float s = (s0+s1) + (s2+s3);
        float mn = fmaxf(m, s);
        float corr = __expf(m - mn);
        float p    = __expf(s - mn);
        l = l*corr + p;
        #pragma unroll
        for (int d = 0; d < 16; d++) {
            float4 tv = vp[d];
            o[4*d+0] = o[4*d+0]*corr + p*tv.x;
            o[4*d+1] = o[4*d+1]*corr + p*tv.y;
            o[4*d+2] = o[4*d+2]*corr + p*tv.z;
            o[4*d+3] = o[4*d+3]*corr + p*tv.w;
        }
        m = mn;
    }

    sm_[tid] = m;
    __syncthreads();
    float gm = -INFINITY;
    for (int t = 0; t < 128; t++) gm = fmaxf(gm, sm_[t]);
    float c = __expf(m - gm);
    sl_[tid] = l * c;
    #pragma unroll
    for (int d = 0; d < HD; d++) red[tid][d] = o[d] * c;
    __syncthreads();

    if (tid < HD) {
        float sum = 0.f, lsum = 0.f;
        for (int t = 0; t < 128; t++) {
            sum  += red[t][tid];
            lsum += sl_[t];
        }
        g_o[base + tid] = sum / lsum;   // token n = 0
    }
}

// ---------------------------------------------------------------------------
extern "C" void kernel_launch(void* const* d_in, const int* in_sizes, int n_in,
                              void* d_out, int out_size) {
    const float* x      = (const float*)d_in[0];
    const float* qkv_w  = (const float*)d_in[1];
    const float* qkv_b  = (const float*)d_in[2];
    const float* proj_w = (const float*)d_in[3];
    const float* proj_b = (const float*)d_in[4];
    const int*   tmask  = (const int*)d_in[5];
    float* out = (float*)d_out;

    const int div_smem = (2*NKEY*HD)*(int)sizeof(float) + NKEY*(int)sizeof(int);
    cudaFuncSetAttribute(div_attn, cudaFuncAttributeMaxDynamicSharedMemorySize, div_smem);

    dim3 qkv_grid((M_ROWS + BM - 1)/BM, QKVDIM/BN);
    qkv_gemm<<<qkv_grid, 256>>>(x, qkv_w, qkv_b);

    cls_attn<<<BDIM*HEADS, 128>>>(tmask);
    div_attn<<<BDIM*HEADS*FRAMES, 256, div_smem>>>(tmask);

    dim3 proj_grid((M_ROWS + BM - 1)/BM, DIM/BN);
    proj_gemm<<<proj_grid, 256>>>(proj_w, proj_b, out);
}

// round 3
// speedup vs baseline: 1.9391x; 1.9391x over previous
#include <cuda_runtime.h>
#include <math.h>

// Problem constants
#define NTOK   3137            // 1 + 16*196
#define BDIM   4
#define HEADS  16
#define HD     64
#define DIM    1024
#define QKVDIM 3072
#define M_ROWS (BDIM*NTOK)     // 12548
#define FRAMES 16
#define SEQ    196
#define NKEY   197             // SEQ + cls

// Scratch (allocation-free rule: __device__ globals)
__device__ float g_q[(size_t)BDIM*HEADS*NTOK*HD];
__device__ float g_k[(size_t)BDIM*HEADS*NTOK*HD];
__device__ float g_v[(size_t)BDIM*HEADS*NTOK*HD];
__device__ float g_o[(size_t)BDIM*HEADS*NTOK*HD];

// ---------------------------------------------------------------------------
// Helpers
// ---------------------------------------------------------------------------
__device__ __forceinline__ unsigned f2tf32(float f) {
    unsigned u;
    asm("cvt.rna.tf32.f32 %0, %1;" : "=r"(u) : "f"(f));
    return u;
}

__device__ __forceinline__ void mma_tf32(float& c0, float& c1, float& c2, float& c3,
                                         unsigned a0, unsigned a1, unsigned a2, unsigned a3,
                                         unsigned b0, unsigned b1) {
    asm("mma.sync.aligned.m16n8k8.row.col.f32.tf32.tf32.f32 "
        "{%0,%1,%2,%3}, {%4,%5,%6,%7}, {%8,%9}, {%0,%1,%2,%3};"
        : "+f"(c0), "+f"(c1), "+f"(c2), "+f"(c3)
        : "r"(a0), "r"(a1), "r"(a2), "r"(a3), "r"(b0), "r"(b1));
}

// Fast exp on the FMA pipe (arg <= ~0; clamped for underflow). ~2e-6 rel err.
__device__ __forceinline__ float fexp(float x) {
    float z = fmaxf(x * 1.4426950408889634f, -126.f);
    float n = rintf(z);
    float f = z - n;
    float p = 1.3333558e-3f;
    p = fmaf(p, f, 9.6181291e-3f);
    p = fmaf(p, f, 5.5504109e-2f);
    p = fmaf(p, f, 2.4022651e-1f);
    p = fmaf(p, f, 6.9314718e-1f);
    p = fmaf(p, f, 1.0f);
    return p * __int_as_float(((int)n + 127) << 23);
}

// ---------------------------------------------------------------------------
// tf32 tensor-core GEMM tiles: BM=128, BN=64, BK=32, 256 threads (8 warps)
// warp grid 4(m) x 2(n); each warp 32x32 via m16n8k8: 2 m-frags x 4 n-frags.
// Smem row-major with pad 4 (36 uints/row = 144B, 16B aligned, conflict-free
// frag loads: bank = (4*row + col) % 32 distinct within each ldq pattern).
// ---------------------------------------------------------------------------
#define BMT 128
#define BNT 64
#define BKT 32
#define KP  36     // BKT + 4

// QKV: out[m][o] = x @ qkv_w^T + b, scattered head-major; q scaled 0.125.
__global__ __launch_bounds__(256) void qkv_gemm_tc(const float* __restrict__ x,
                                                   const float* __restrict__ w,
                                                   const float* __restrict__ bias) {
    __shared__ unsigned As[BMT][KP];
    __shared__ unsigned Bs[BNT][KP];
    const int tid  = threadIdx.x;
    const int warp = tid >> 5, lane = tid & 31;
    const int g    = lane >> 2, tq = lane & 3;
    const int m0   = (warp >> 1) * 32, n0 = (warp & 1) * 32;
    const int tm0  = blockIdx.x * BMT, tn0 = blockIdx.y * BNT;

    float acc[2][4][4];
    #pragma unroll
    for (int i = 0; i < 2; i++)
        #pragma unroll
        for (int j = 0; j < 4; j++)
            #pragma unroll
            for (int r = 0; r < 4; r++) acc[i][j][r] = 0.f;

    for (int k0 = 0; k0 < DIM; k0 += BKT) {
        // A: 128 rows x 8 float4 = 1024 float4-loads, 4 per thread
        #pragma unroll
        for (int l = 0; l < 4; l++) {
            int idx = tid + l*256;
            int row = idx >> 3;
            int kc  = (idx & 7) << 2;
            int gm  = tm0 + row;
            float4 t = make_float4(0.f,0.f,0.f,0.f);
            if (gm < M_ROWS) t = *(const float4*)(x + (size_t)gm*DIM + k0 + kc);
            uint4 u = make_uint4(f2tf32(t.x), f2tf32(t.y), f2tf32(t.z), f2tf32(t.w));
            *(uint4*)&As[row][kc] = u;
        }
        // B: 64 rows x 8 float4 = 512, 2 per thread
        #pragma unroll
        for (int l = 0; l < 2; l++) {
            int idx = tid + l*256;
            int row = idx >> 3;
            int kc  = (idx & 7) << 2;
            float4 t = *(const float4*)(w + (size_t)(tn0+row)*DIM + k0 + kc);
            uint4 u = make_uint4(f2tf32(t.x), f2tf32(t.y), f2tf32(t.z), f2tf32(t.w));
            *(uint4*)&Bs[row][kc] = u;
        }
        __syncthreads();

        #pragma unroll
        for (int ks = 0; ks < 4; ks++) {
            int kk = ks * 8;
            unsigned a[2][4], b[4][2];
            #pragma unroll
            for (int i = 0; i < 2; i++) {
                a[i][0] = As[m0 + i*16 + g    ][kk + tq];
                a[i][1] = As[m0 + i*16 + g + 8][kk + tq];
                a[i][2] = As[m0 + i*16 + g    ][kk + tq + 4];
                a[i][3] = As[m0 + i*16 + g + 8][kk + tq + 4];
            }
            #pragma unroll
            for (int j = 0; j < 4; j++) {
                b[j][0] = Bs[n0 + j*8 + g][kk + tq];
                b[j][1] = Bs[n0 + j*8 + g][kk + tq + 4];
            }
            #pragma unroll
            for (int i = 0; i < 2; i++)
                #pragma unroll
                for (int j = 0; j < 4; j++)
                    mma_tf32(acc[i][j][0], acc[i][j][1], acc[i][j][2], acc[i][j][3],
                             a[i][0], a[i][1], a[i][2], a[i][3], b[j][0], b[j][1]);
        }
        __syncthreads();
    }

    // Epilogue: c0,c1 -> row g, cols 2tq,2tq+1 ; c2,c3 -> row g+8
    #pragma unroll
    for (int i = 0; i < 2; i++) {
        #pragma unroll
        for (int half = 0; half < 2; half++) {
            int gm = tm0 + m0 + i*16 + g + half*8;
            if (gm >= M_ROWS) continue;
            int b_ = gm / NTOK;
            int n_ = gm - b_*NTOK;
            #pragma unroll
            for (int j = 0; j < 4; j++) {
                #pragma unroll
                for (int c = 0; c < 2; c++) {
                    int gn = tn0 + n0 + j*8 + 2*tq + c;
                    float val = acc[i][j][half*2 + c] + bias[gn];
                    int part = gn >> 10;
                    int rem  = gn & 1023;
                    int h = rem >> 6;
                    int d = rem & 63;
                    size_t off = (((size_t)(b_*HEADS + h))*NTOK + n_)*HD + d;
                    if (part == 0)      g_q[off] = val * 0.125f;
                    else if (part == 1) g_k[off] = val;
                    else                g_v[off] = val;
                }
            }
        }
    }
}

// Proj: out = gather(g_o) @ proj_w^T + b
__global__ __launch_bounds__(256) void proj_gemm_tc(const float* __restrict__ w,
                                                    const float* __restrict__ bias,
                                                    float* __restrict__ out) {
    __shared__ unsigned As[BMT][KP];
    __shared__ unsigned Bs[BNT][KP];
    const int tid  = threadIdx.x;
    const int warp = tid >> 5, lane = tid & 31;
    const int g    = lane >> 2, tq = lane & 3;
    const int m0   = (warp >> 1) * 32, n0 = (warp & 1) * 32;
    const int tm0  = blockIdx.x * BMT, tn0 = blockIdx.y * BNT;

    // hoist A-row decomposition (4 loads per thread, fixed rows)
    int a_b[4], a_n[4], a_ok[4];
    #pragma unroll
    for (int l = 0; l < 4; l++) {
        int row = (tid + l*256) >> 3;
        int gm  = tm0 + row;
        a_ok[l] = (gm < M_ROWS);
        int bb  = a_ok[l] ? (gm / NTOK) : 0;
        a_b[l] = bb;
        a_n[l] = gm - bb*NTOK;
    }

    float acc[2][4][4];
    #pragma unroll
    for (int i = 0; i < 2; i++)
        #pragma unroll
        for (int j = 0; j < 4; j++)
            #pragma unroll
            for (int r = 0; r < 4; r++) acc[i][j][r] = 0.f;

    for (int k0 = 0; k0 < DIM; k0 += BKT) {
        #pragma unroll
        for (int l = 0; l < 4; l++) {
            int idx = tid + l*256;
            int row = idx >> 3;
            int kc  = (idx & 7) << 2;
            float4 t = make_float4(0.f,0.f,0.f,0.f);
            if (a_ok[l]) {
                int k = k0 + kc;
                int h = k >> 6;
                int d = k & 63;
                t = *(const float4*)(g_o + (((size_t)(a_b[l]*HEADS + h))*NTOK + a_n[l])*HD + d);
            }
            uint4 u = make_uint4(f2tf32(t.x), f2tf32(t.y), f2tf32(t.z), f2tf32(t.w));
            *(uint4*)&As[row][kc] = u;
        }
        #pragma unroll
        for (int l = 0; l < 2; l++) {
            int idx = tid + l*256;
            int row = idx >> 3;
            int kc  = (idx & 7) << 2;
            float4 t = *(const float4*)(w + (size_t)(tn0+row)*DIM + k0 + kc);
            uint4 u = make_uint4(f2tf32(t.x), f2tf32(t.y), f2tf32(t.z), f2tf32(t.w));
            *(uint4*)&Bs[row][kc] = u;
        }
        __syncthreads();

        #pragma unroll
        for (int ks = 0; ks < 4; ks++) {
            int kk = ks * 8;
            unsigned a[2][4], b[4][2];
            #pragma unroll
            for (int i = 0; i < 2; i++) {
                a[i][0] = As[m0 + i*16 + g    ][kk + tq];
                a[i][1] = As[m0 + i*16 + g + 8][kk + tq];
                a[i][2] = As[m0 + i*16 + g    ][kk + tq + 4];
                a[i][3] = As[m0 + i*16 + g + 8][kk + tq + 4];
            }
            #pragma unroll
            for (int j = 0; j < 4; j++) {
                b[j][0] = Bs[n0 + j*8 + g][kk + tq];
                b[j][1] = Bs[n0 + j*8 + g][kk + tq + 4];
            }
            #pragma unroll
            for (int i = 0; i < 2; i++)
                #pragma unroll
                for (int j = 0; j < 4; j++)
                    mma_tf32(acc[i][j][0], acc[i][j][1], acc[i][j][2], acc[i][j][3],
                             a[i][0], a[i][1], a[i][2], a[i][3], b[j][0], b[j][1]);
        }
        __syncthreads();
    }

    #pragma unroll
    for (int i = 0; i < 2; i++) {
        #pragma unroll
        for (int half = 0; half < 2; half++) {
            int gm = tm0 + m0 + i*16 + g + half*8;
            if (gm >= M_ROWS) continue;
            #pragma unroll
            for (int j = 0; j < 4; j++) {
                #pragma unroll
                for (int c = 0; c < 2; c++) {
                    int gn = tn0 + n0 + j*8 + 2*tq + c;
                    out[(size_t)gm*DIM + gn] = acc[i][j][half*2 + c] + bias[gn];
                }
            }
        }
    }
}

// ---------------------------------------------------------------------------
// Divided (spatial) attention: 1 CTA per group g = bh*16 + frame.
// One thread per query; K/V staged in smem (broadcast reads); deferred-rescale
// online softmax with FMA-pipe exp.
// ---------------------------------------------------------------------------
__global__ __launch_bounds__(256) void div_attn(const int* __restrict__ mask) {
    extern __shared__ float sh[];
    float* kk = sh;                       // NKEY*HD
    float* vv = sh + NKEY*HD;             // NKEY*HD
    int*   mk = (int*)(vv + NKEY*HD);     // NKEY

    const int grp = blockIdx.x;
    const int bh  = grp >> 4;
    const int fi  = grp & 15;
    const int b   = bh >> 4;
    const int tid = threadIdx.x;

    for (int idx = tid; idx < NKEY*HD; idx += 256) {
        int j = idx >> 6;
        int d = idx & 63;
        int tok = (j == 0) ? 0 : (fi*SEQ + j);
        size_t off = ((size_t)bh*NTOK + tok)*HD + d;
        kk[idx] = g_k[off];
        vv[idx] = g_v[off];
    }
    for (int j = tid; j < NKEY; j += 256) {
        int tok = (j == 0) ? 0 : (fi*SEQ + j);
        mk[j] = mask[b*NTOK + tok];
    }
    __syncthreads();

    if (tid < SEQ) {
        int qi = 1 + fi*SEQ + tid;
        size_t qoff = ((size_t)bh*NTOK + qi)*HD;
        float q[HD];
        #pragma unroll
        for (int d = 0; d < HD; d += 4) {
            float4 t = *(const float4*)(g_q + qoff + d);
            q[d] = t.x; q[d+1] = t.y; q[d+2] = t.z; q[d+3] = t.w;
        }
        float o[HD];
        #pragma unroll
        for (int d = 0; d < HD; d++) o[d] = 0.f;
        float m = -INFINITY, l = 0.f;

        const float4* kk4 = (const float4*)kk;
        const float4* vv4 = (const float4*)vv;
        for (int j = 0; j < NKEY; j++) {
            if (mk[j] == 0) continue;
            float s0 = 0.f, s1 = 0.f, s2 = 0.f, s3 = 0.f;
            #pragma unroll
            for (int d = 0; d < 16; d++) {
                float4 kv = kk4[j*16 + d];
                s0 = fmaf(q[4*d+0], kv.x, s0);
                s1 = fmaf(q[4*d+1], kv.y, s1);
                s2 = fmaf(q[4*d+2], kv.z, s2);
                s3 = fmaf(q[4*d+3], kv.w, s3);
            }
            float s = (s0+s1) + (s2+s3);
            if (s <= m) {
                float p = fexp(s - m);
                l += p;
                #pragma unroll
                for (int d = 0; d < 16; d++) {
                    float4 tv = vv4[j*16 + d];
                    o[4*d+0] = fmaf(p, tv.x, o[4*d+0]);
                    o[4*d+1] = fmaf(p, tv.y, o[4*d+1]);
                    o[4*d+2] = fmaf(p, tv.z, o[4*d+2]);
                    o[4*d+3] = fmaf(p, tv.w, o[4*d+3]);
                }
            } else {
                float corr = fexp(m - s);
                m = s;
                l = fmaf(l, corr, 1.f);
                #pragma unroll
                for (int d = 0; d < 16; d++) {
                    float4 tv = vv4[j*16 + d];
                    o[4*d+0] = fmaf(o[4*d+0], corr, tv.x);
                    o[4*d+1] = fmaf(o[4*d+1], corr, tv.y);
                    o[4*d+2] = fmaf(o[4*d+2], corr, tv.z);
                    o[4*d+3] = fmaf(o[4*d+3], corr, tv.w);
                }
            }
        }
        float inv = 1.f / l;
        #pragma unroll
        for (int d = 0; d < HD; d += 4) {
            float4 t = make_float4(o[d]*inv, o[d+1]*inv, o[d+2]*inv, o[d+3]*inv);
            *(float4*)(g_o + qoff + d) = t;
        }
    }
}

// ---------------------------------------------------------------------------
// cls-token attention: 1 CTA per (b,h); 128 threads split the keys.
// ---------------------------------------------------------------------------
__global__ __launch_bounds__(128) void cls_attn(const int* __restrict__ mask) {
    __shared__ float red[128][HD+1];
    __shared__ float sm_[128];
    __shared__ float sl_[128];

    const int bh  = blockIdx.x;
    const int b   = bh >> 4;
    const int tid = threadIdx.x;
    const size_t base = (size_t)bh*NTOK*HD;

    float q[HD];
    #pragma unroll
    for (int d = 0; d < HD; d += 4) {
        float4 t = *(const float4*)(g_q + base + d);
        q[d] = t.x; q[d+1] = t.y; q[d+2] = t.z; q[d+3] = t.w;
    }
    float o[HD];
    #pragma unroll
    for (int d = 0; d < HD; d++) o[d] = 0.f;
    float m = -INFINITY, l = 0.f;

    for (int j = tid; j < NTOK; j += 128) {
        if (mask[b*NTOK + j] == 0) continue;
        const float4* kp = (const float4*)(g_k + base + (size_t)j*HD);
        const float4* vp = (const float4*)(g_v + base + (size_t)j*HD);
        float s0 = 0.f, s1 = 0.f, s2 = 0.f, s3 = 0.f;
        #pragma unroll
        for (int d = 0; d < 16; d++) {
            float4 kv = kp[d];
            s0 = fmaf(q[4*d+0], kv.x, s0);
            s1 = fmaf(q[4*d+1], kv.y, s1);
            s2 = fmaf(q[4*d+2], kv.z, s2);
            s3 = fmaf(q[4*d+3], kv.w, s3);
        }
        float s = (s0+s1) + (s2+s3);
        if (s <= m) {
            float p = fexp(s - m);
            l += p;
            #pragma unroll
            for (int d = 0; d < 16; d++) {
                float4 tv = vp[d];
                o[4*d+0] = fmaf(p, tv.x, o[4*d+0]);
                o[4*d+1] = fmaf(p, tv.y, o[4*d+1]);
                o[4*d+2] = fmaf(p, tv.z, o[4*d+2]);
                o[4*d+3] = fmaf(p, tv.w, o[4*d+3]);
            }
        } else {
            float corr = fexp(m - s);
            m = s;
            l = fmaf(l, corr, 1.f);
            #pragma unroll
            for (int d = 0; d < 16; d++) {
                float4 tv = vp[d];
                o[4*d+0] = fmaf(o[4*d+0], corr, tv.x);
                o[4*d+1] = fmaf(o[4*d+1], corr, tv.y);
                o[4*d+2] = fmaf(o[4*d+2], corr, tv.z);
                o[4*d+3] = fmaf(o[4*d+3], corr, tv.w);
            }
        }
    }

    sm_[tid] = m;
    __syncthreads();
    float gm = -INFINITY;
    for (int t = 0; t < 128; t++) gm = fmaxf(gm, sm_[t]);
    float c = fexp(m - gm);
    sl_[tid] = l * c;
    #pragma unroll
    for (int d = 0; d < HD; d++) red[tid][d] = o[d] * c;
    __syncthreads();

    if (tid < HD) {
        float sum = 0.f, lsum = 0.f;
        for (int t = 0; t < 128; t++) {
            sum  += red[t][tid];
            lsum += sl_[t];
        }
        g_o[base + tid] = sum / lsum;   // token n = 0
    }
}

// ---------------------------------------------------------------------------
extern "C" void kernel_launch(void* const* d_in, const int* in_sizes, int n_in,
                              void* d_out, int out_size) {
    const float* x      = (const float*)d_in[0];
    const float* qkv_w  = (const float*)d_in[1];
    const float* qkv_b  = (const float*)d_in[2];
    const float* proj_w = (const float*)d_in[3];
    const float* proj_b = (const float*)d_in[4];
    const int*   tmask  = (const int*)d_in[5];
    float* out = (float*)d_out;

    const int div_smem = (2*NKEY*HD)*(int)sizeof(float) + NKEY*(int)sizeof(int);
    cudaFuncSetAttribute(div_attn, cudaFuncAttributeMaxDynamicSharedMemorySize, div_smem);

    dim3 qkv_grid((M_ROWS + BMT - 1)/BMT, QKVDIM/BNT);
    qkv_gemm_tc<<<qkv_grid, 256>>>(x, qkv_w, qkv_b);

    cls_attn<<<BDIM*HEADS, 128>>>(tmask);
    div_attn<<<BDIM*HEADS*FRAMES, 256, div_smem>>>(tmask);

    dim3 proj_grid((M_ROWS + BMT - 1)/BMT, DIM/BNT);
    proj_gemm_tc<<<proj_grid, 256>>>(proj_w, proj_b, out);
}